// round 16
// baseline (speedup 1.0000x reference)
#include <cuda_runtime.h>
#include <cuda_bf16.h>
#include <math_constants.h>

// MASS_18897856102446: fused weighted-sq-dist attention — FINAL
// out[b,n] = out_dist[b,n] * softmax_n(-(att_dist[b,n]*mask[b,n]))
// B=1024, N=200, E=128 (fp32). HBM-bound: m + m_c = ~210MB streamed once.
// Design (converged over R1-R15):
//  - 128-thr CTAs, grid=1024 -> 7 CTAs/SM, SINGLE WAVE (the big win, R6)
//  - expanded-square algebra: sq-dists -> Cq + sum m(v*m - 2u), shared
//    u/v/Cq for both tensors => 16 FFMA/row (R4/R5)
//  - 16-float4 front-batched load groups: max per-warp MLP under the
//    72-reg / 7-CTA budget (R3; R8 proved smaller batches lose)
//  - pair-merging tree reduction: 31 SHFL for 16 warp-sums (R7)
//  - group-0 loads hoisted above the prologue (R10)
//  - epilogue double-buffered s_red: one fewer barrier (R16)
// Ceiling: 6.1 TB/s achieved == pattern limit (verified vs LDGSTS pipeline,
// 5-warp variant, and bulk-TMA in R11-R14). 97% streaming efficiency.

constexpr int N_ = 200;
constexpr int E_ = 128;
constexpr int NWARP = 4;
constexpr int NTHR = NWARP * 32;   // 128

__global__ __launch_bounds__(NTHR, 7)
void mass_kernel(const float* __restrict__ q,
                 const float* __restrict__ q_p,
                 const float* __restrict__ m,
                 const float* __restrict__ m_c,
                 const float* __restrict__ A1,
                 const float* __restrict__ A2,
                 const float* __restrict__ biases,
                 const float* __restrict__ mask,
                 float* __restrict__ out)
{
    const int b    = blockIdx.x;
    const int tid  = threadIdx.x;
    const int warp = tid >> 5;
    const int lane = tid & 31;

    __shared__ float4 s_v[E_ / 4], s_m2u[E_ / 4];
    __shared__ float  s_cq[NWARP];
    __shared__ float  s_logit[N_], s_outd[N_];
    __shared__ float  s_b2[N_], s_mk[N_];
    __shared__ float  s_red[NWARP], s_red2[NWARP];

    const float4* __restrict__ m4 = reinterpret_cast<const float4*>(m   + (size_t)b * N_ * E_);
    const float4* __restrict__ c4 = reinterpret_cast<const float4*>(m_c + (size_t)b * N_ * E_);

    // ── Hoisted group-0 loads: in flight while the prologue runs. ──
    const int nb0 = warp;   // k = 0
    const float4 mv0 = m4[(nb0 + 0 * NWARP) * (E_ / 4) + lane];
    const float4 mv1 = m4[(nb0 + 1 * NWARP) * (E_ / 4) + lane];
    const float4 mv2 = m4[(nb0 + 2 * NWARP) * (E_ / 4) + lane];
    const float4 mv3 = m4[(nb0 + 3 * NWARP) * (E_ / 4) + lane];
    const float4 mv4 = m4[(nb0 + 4 * NWARP) * (E_ / 4) + lane];
    const float4 mv5 = m4[(nb0 + 5 * NWARP) * (E_ / 4) + lane];
    const float4 mv6 = m4[(nb0 + 6 * NWARP) * (E_ / 4) + lane];
    const float4 mv7 = m4[(nb0 + 7 * NWARP) * (E_ / 4) + lane];
    const float4 cv0 = c4[(nb0 + 0 * NWARP) * (E_ / 4) + lane];
    const float4 cv1 = c4[(nb0 + 1 * NWARP) * (E_ / 4) + lane];
    const float4 cv2 = c4[(nb0 + 2 * NWARP) * (E_ / 4) + lane];
    const float4 cv3 = c4[(nb0 + 3 * NWARP) * (E_ / 4) + lane];
    const float4 cv4 = c4[(nb0 + 4 * NWARP) * (E_ / 4) + lane];
    const float4 cv5 = c4[(nb0 + 5 * NWARP) * (E_ / 4) + lane];
    const float4 cv6 = c4[(nb0 + 6 * NWARP) * (E_ / 4) + lane];
    const float4 cv7 = c4[(nb0 + 7 * NWARP) * (E_ / 4) + lane];

    // ── Prologue (overlapped with in-flight group-0 loads). ──
    {
        const float a1 = A1[tid];
        const float a2 = A2[tid];
        const float a1s = a1 * a1, a2s = a2 * a2;
        const float qv  = q  [(size_t)b * E_ + tid];
        const float qpv = q_p[(size_t)b * E_ + tid];
        reinterpret_cast<float*>(s_v)  [tid] = a1s + a2s;
        reinterpret_cast<float*>(s_m2u)[tid] = -2.f * (a1s * qv + a2s * qpv);

        s_b2[tid] = 2.f * biases[(size_t)b * N_ + tid];
        s_mk[tid] = mask  [(size_t)b * N_ + tid];
        if (tid + NTHR < N_) {
            s_b2[tid + NTHR] = 2.f * biases[(size_t)b * N_ + tid + NTHR];
            s_mk[tid + NTHR] = mask  [(size_t)b * N_ + tid + NTHR];
        }

        float c = a1s * qv * qv + a2s * qpv * qpv;
        #pragma unroll
        for (int o = 16; o; o >>= 1)
            c += __shfl_xor_sync(0xffffffffu, c, o);
        if (lane == 0) s_cq[warp] = c;
    }
    __syncthreads();

    const float4 vv = s_v[lane];
    const float4 mu = s_m2u[lane];
    const float  Cq = s_cq[0] + s_cq[1] + s_cq[2] + s_cq[3];

    auto body = [&](const float4 mv, const float4 cv, float& sa, float& so) {
        float t;
        t = fmaf(vv.x, mv.x, mu.x); sa = mv.x * t;
        t = fmaf(vv.y, mv.y, mu.y); sa = fmaf(mv.y, t, sa);
        t = fmaf(vv.z, mv.z, mu.z); sa = fmaf(mv.z, t, sa);
        t = fmaf(vv.w, mv.w, mu.w); sa = fmaf(mv.w, t, sa);
        t = fmaf(vv.x, cv.x, mu.x); so = cv.x * t;
        t = fmaf(vv.y, cv.y, mu.y); so = fmaf(cv.y, t, so);
        t = fmaf(vv.z, cv.z, mu.z); so = fmaf(cv.z, t, so);
        t = fmaf(vv.w, cv.w, mu.w); so = fmaf(cv.w, t, so);
    };

    auto finish1 = [&](int n, float sa, float so) {
        #pragma unroll
        for (int o = 16; o; o >>= 1) {
            sa += __shfl_xor_sync(0xffffffffu, sa, o);
            so += __shfl_xor_sync(0xffffffffu, so, o);
        }
        if (lane == 0) {
            const float add = Cq + s_b2[n];
            const float mk  = s_mk[n];
            s_logit[n] = -((sa + add) * mk);
            s_outd[n]  = (so + add) * mk;
        }
    };

    const unsigned FULL = 0xffffffffu;
    const bool lo16 = (lane & 16) == 0;
    const bool b3z  = (lane & 8)  == 0;
    const bool b2z  = (lane & 4)  == 0;
    const bool b1z  = (lane & 2)  == 0;

    auto reduceG = [&](int nb,
                       float sa0, float so0, float sa1, float so1,
                       float sa2, float so2, float sa3, float so3,
                       float sa4, float so4, float sa5, float so5,
                       float sa6, float so6, float sa7, float so7) {
        float A, B;
        A = sa0 + __shfl_xor_sync(FULL, sa0, 16);
        B = so0 + __shfl_xor_sync(FULL, so0, 16);
        const float r0 = lo16 ? A : B;
        A = sa1 + __shfl_xor_sync(FULL, sa1, 16);
        B = so1 + __shfl_xor_sync(FULL, so1, 16);
        const float r1 = lo16 ? A : B;
        A = sa2 + __shfl_xor_sync(FULL, sa2, 16);
        B = so2 + __shfl_xor_sync(FULL, so2, 16);
        const float r2 = lo16 ? A : B;
        A = sa3 + __shfl_xor_sync(FULL, sa3, 16);
        B = so3 + __shfl_xor_sync(FULL, so3, 16);
        const float r3 = lo16 ? A : B;
        A = sa4 + __shfl_xor_sync(FULL, sa4, 16);
        B = so4 + __shfl_xor_sync(FULL, so4, 16);
        const float r4 = lo16 ? A : B;
        A = sa5 + __shfl_xor_sync(FULL, sa5, 16);
        B = so5 + __shfl_xor_sync(FULL, so5, 16);
        const float r5 = lo16 ? A : B;
        A = sa6 + __shfl_xor_sync(FULL, sa6, 16);
        B = so6 + __shfl_xor_sync(FULL, so6, 16);
        const float r6 = lo16 ? A : B;
        A = sa7 + __shfl_xor_sync(FULL, sa7, 16);
        B = so7 + __shfl_xor_sync(FULL, so7, 16);
        const float r7 = lo16 ? A : B;

        A = r0 + __shfl_xor_sync(FULL, r0, 8);
        B = r1 + __shfl_xor_sync(FULL, r1, 8);
        const float s0 = b3z ? A : B;
        A = r2 + __shfl_xor_sync(FULL, r2, 8);
        B = r3 + __shfl_xor_sync(FULL, r3, 8);
        const float s1 = b3z ? A : B;
        A = r4 + __shfl_xor_sync(FULL, r4, 8);
        B = r5 + __shfl_xor_sync(FULL, r5, 8);
        const float s2 = b3z ? A : B;
        A = r6 + __shfl_xor_sync(FULL, r6, 8);
        B = r7 + __shfl_xor_sync(FULL, r7, 8);
        const float s3 = b3z ? A : B;

        A = s0 + __shfl_xor_sync(FULL, s0, 4);
        B = s1 + __shfl_xor_sync(FULL, s1, 4);
        const float t0 = b2z ? A : B;
        A = s2 + __shfl_xor_sync(FULL, s2, 4);
        B = s3 + __shfl_xor_sync(FULL, s3, 4);
        const float t1 = b2z ? A : B;

        A = t0 + __shfl_xor_sync(FULL, t0, 2);
        B = t1 + __shfl_xor_sync(FULL, t1, 2);
        const float u = b1z ? A : B;

        const float f = u + __shfl_xor_sync(FULL, u, 1);

        if ((lane & 1) == 0) {
            const int row = 4 * ((lane >> 1) & 1) + 2 * ((lane >> 2) & 1)
                          + ((lane >> 3) & 1);
            const int n   = nb + row * NWARP;
            const float val = (f + Cq + s_b2[n]) * s_mk[n];
            if (lo16) s_logit[n] = -val;
            else      s_outd[n]  =  val;
        }
    };

    // ── Group 0 (preloaded) ──
    {
        float sa0, so0, sa1, so1, sa2, so2, sa3, so3;
        float sa4, so4, sa5, so5, sa6, so6, sa7, so7;
        body(mv0, cv0, sa0, so0);
        body(mv1, cv1, sa1, so1);
        body(mv2, cv2, sa2, so2);
        body(mv3, cv3, sa3, so3);
        body(mv4, cv4, sa4, so4);
        body(mv5, cv5, sa5, so5);
        body(mv6, cv6, sa6, so6);
        body(mv7, cv7, sa7, so7);
        reduceG(nb0, sa0, so0, sa1, so1, sa2, so2, sa3, so3,
                     sa4, so4, sa5, so5, sa6, so6, sa7, so7);
    }

    // ── Groups 1..5 ──
    #pragma unroll 1
    for (int k = 8; k < 48; k += 8) {
        const int nb = warp + k * NWARP;

        const float4 Mv0 = m4[(nb + 0 * NWARP) * (E_ / 4) + lane];
        const float4 Mv1 = m4[(nb + 1 * NWARP) * (E_ / 4) + lane];
        const float4 Mv2 = m4[(nb + 2 * NWARP) * (E_ / 4) + lane];
        const float4 Mv3 = m4[(nb + 3 * NWARP) * (E_ / 4) + lane];
        const float4 Mv4 = m4[(nb + 4 * NWARP) * (E_ / 4) + lane];
        const float4 Mv5 = m4[(nb + 5 * NWARP) * (E_ / 4) + lane];
        const float4 Mv6 = m4[(nb + 6 * NWARP) * (E_ / 4) + lane];
        const float4 Mv7 = m4[(nb + 7 * NWARP) * (E_ / 4) + lane];
        const float4 Cv0 = c4[(nb + 0 * NWARP) * (E_ / 4) + lane];
        const float4 Cv1 = c4[(nb + 1 * NWARP) * (E_ / 4) + lane];
        const float4 Cv2 = c4[(nb + 2 * NWARP) * (E_ / 4) + lane];
        const float4 Cv3 = c4[(nb + 3 * NWARP) * (E_ / 4) + lane];
        const float4 Cv4 = c4[(nb + 4 * NWARP) * (E_ / 4) + lane];
        const float4 Cv5 = c4[(nb + 5 * NWARP) * (E_ / 4) + lane];
        const float4 Cv6 = c4[(nb + 6 * NWARP) * (E_ / 4) + lane];
        const float4 Cv7 = c4[(nb + 7 * NWARP) * (E_ / 4) + lane];

        float sa0, so0, sa1, so1, sa2, so2, sa3, so3;
        float sa4, so4, sa5, so5, sa6, so6, sa7, so7;
        body(Mv0, Cv0, sa0, so0);
        body(Mv1, Cv1, sa1, so1);
        body(Mv2, Cv2, sa2, so2);
        body(Mv3, Cv3, sa3, so3);
        body(Mv4, Cv4, sa4, so4);
        body(Mv5, Cv5, sa5, so5);
        body(Mv6, Cv6, sa6, so6);
        body(Mv7, Cv7, sa7, so7);

        reduceG(nb, sa0, so0, sa1, so1, sa2, so2, sa3, so3,
                    sa4, so4, sa5, so5, sa6, so6, sa7, so7);
    }
    // Tail rows j = 48, 49.
    {
        const int n0 = warp + 48 * NWARP;
        const int n1 = warp + 49 * NWARP;
        const float4 Mv0 = m4[n0 * (E_ / 4) + lane];
        const float4 Mv1 = m4[n1 * (E_ / 4) + lane];
        const float4 Cv0 = c4[n0 * (E_ / 4) + lane];
        const float4 Cv1 = c4[n1 * (E_ / 4) + lane];
        float sa0, so0, sa1, so1;
        body(Mv0, Cv0, sa0, so0);
        body(Mv1, Cv1, sa1, so1);
        finish1(n0, sa0, so0);
        finish1(n1, sa1, so1);
    }
    __syncthreads();

    // Block softmax over N_=200 with 128 threads; double-buffered warp
    // partials (s_red for max, s_red2 for sum) -> one fewer barrier.
    const int  n2ok = (tid + NTHR) < N_;
    const float v1 = s_logit[tid];
    const float v2 = n2ok ? s_logit[tid + NTHR] : -CUDART_INF_F;

    float wm = fmaxf(v1, v2);
    #pragma unroll
    for (int o = 16; o; o >>= 1)
        wm = fmaxf(wm, __shfl_xor_sync(0xffffffffu, wm, o));
    if (lane == 0) s_red[warp] = wm;
    __syncthreads();

    const float mx = fmaxf(fmaxf(s_red[0], s_red[1]), fmaxf(s_red[2], s_red[3]));

    const float ex1 = __expf(v1 - mx);
    const float ex2 = n2ok ? __expf(v2 - mx) : 0.f;

    float ws = ex1 + ex2;
    #pragma unroll
    for (int o = 16; o; o >>= 1)
        ws += __shfl_xor_sync(0xffffffffu, ws, o);
    if (lane == 0) s_red2[warp] = ws;
    __syncthreads();

    const float inv = 1.f / (s_red2[0] + s_red2[1] + s_red2[2] + s_red2[3]);

    out[(size_t)b * N_ + tid] = s_outd[tid] * ex1 * inv;
    if (n2ok)
        out[(size_t)b * N_ + tid + NTHR] = s_outd[tid + NTHR] * ex2 * inv;
}

extern "C" void kernel_launch(void* const* d_in, const int* in_sizes, int n_in,
                              void* d_out, int out_size)
{
    const float* q      = (const float*)d_in[0];
    const float* q_p    = (const float*)d_in[1];
    const float* m      = (const float*)d_in[2];
    const float* m_c    = (const float*)d_in[3];
    const float* A1     = (const float*)d_in[4];
    const float* A2     = (const float*)d_in[5];
    const float* biases = (const float*)d_in[6];
    const float* mask   = (const float*)d_in[7];
    float* out = (float*)d_out;

    const int B = in_sizes[0] / E_;   // 1024
    mass_kernel<<<B, NTHR>>>(q, q_p, m, m_c, A1, A2, biases, mask, out);
}

// round 17
// speedup vs baseline: 1.0199x; 1.0199x over previous
#include <cuda_runtime.h>
#include <cuda_bf16.h>
#include <math_constants.h>

// MASS_18897856102446: fused weighted-sq-dist attention — FINAL (best-measured)
// out[b,n] = out_dist[b,n] * softmax_n(-(att_dist[b,n]*mask[b,n]))
// B=1024, N=200, E=128 (fp32). HBM-bound: m + m_c = ~210MB streamed once.
// Design (converged over 16 rounds):
//  - 128-thr CTAs, grid=1024 -> 7 CTAs/SM, SINGLE WAVE (R6, biggest win)
//  - expanded-square algebra: sq-dists -> Cq + sum m(v*m - 2u), shared
//    u/v/Cq for both tensors => 16 FFMA/row (R4/R5)
//  - 16-float4 front-batched load groups: max per-warp MLP at 72 regs
//    (R3; R8 proved splitting the batch loses)
//  - pair-merging tree reduction: 31 SHFL for 16 warp-sums (R7)
//  - group-0 loads hoisted above the prologue (R10)
// Ceiling: 6.1 TB/s achieved == pattern limit (invariant across LDG /
// LDGSTS / 5-warp / bulk-TMA in R11-R14). 97% streaming efficiency:
// 35.3us kernel vs 34.4us pure-transfer floor.

constexpr int N_ = 200;
constexpr int E_ = 128;
constexpr int NWARP = 4;
constexpr int NTHR = NWARP * 32;   // 128

__global__ __launch_bounds__(NTHR, 7)
void mass_kernel(const float* __restrict__ q,
                 const float* __restrict__ q_p,
                 const float* __restrict__ m,
                 const float* __restrict__ m_c,
                 const float* __restrict__ A1,
                 const float* __restrict__ A2,
                 const float* __restrict__ biases,
                 const float* __restrict__ mask,
                 float* __restrict__ out)
{
    const int b    = blockIdx.x;
    const int tid  = threadIdx.x;
    const int warp = tid >> 5;
    const int lane = tid & 31;

    __shared__ float4 s_v[E_ / 4], s_m2u[E_ / 4];
    __shared__ float  s_cq[NWARP];
    __shared__ float  s_logit[N_], s_outd[N_];
    __shared__ float  s_b2[N_], s_mk[N_];
    __shared__ float  s_red[NWARP];

    const float4* __restrict__ m4 = reinterpret_cast<const float4*>(m   + (size_t)b * N_ * E_);
    const float4* __restrict__ c4 = reinterpret_cast<const float4*>(m_c + (size_t)b * N_ * E_);

    // ── Hoisted group-0 loads: in flight while the prologue runs. ──
    const int nb0 = warp;   // k = 0
    const float4 mv0 = m4[(nb0 + 0 * NWARP) * (E_ / 4) + lane];
    const float4 mv1 = m4[(nb0 + 1 * NWARP) * (E_ / 4) + lane];
    const float4 mv2 = m4[(nb0 + 2 * NWARP) * (E_ / 4) + lane];
    const float4 mv3 = m4[(nb0 + 3 * NWARP) * (E_ / 4) + lane];
    const float4 mv4 = m4[(nb0 + 4 * NWARP) * (E_ / 4) + lane];
    const float4 mv5 = m4[(nb0 + 5 * NWARP) * (E_ / 4) + lane];
    const float4 mv6 = m4[(nb0 + 6 * NWARP) * (E_ / 4) + lane];
    const float4 mv7 = m4[(nb0 + 7 * NWARP) * (E_ / 4) + lane];
    const float4 cv0 = c4[(nb0 + 0 * NWARP) * (E_ / 4) + lane];
    const float4 cv1 = c4[(nb0 + 1 * NWARP) * (E_ / 4) + lane];
    const float4 cv2 = c4[(nb0 + 2 * NWARP) * (E_ / 4) + lane];
    const float4 cv3 = c4[(nb0 + 3 * NWARP) * (E_ / 4) + lane];
    const float4 cv4 = c4[(nb0 + 4 * NWARP) * (E_ / 4) + lane];
    const float4 cv5 = c4[(nb0 + 5 * NWARP) * (E_ / 4) + lane];
    const float4 cv6 = c4[(nb0 + 6 * NWARP) * (E_ / 4) + lane];
    const float4 cv7 = c4[(nb0 + 7 * NWARP) * (E_ / 4) + lane];

    // ── Prologue (overlapped with in-flight group-0 loads). ──
    {
        const float a1 = A1[tid];
        const float a2 = A2[tid];
        const float a1s = a1 * a1, a2s = a2 * a2;
        const float qv  = q  [(size_t)b * E_ + tid];
        const float qpv = q_p[(size_t)b * E_ + tid];
        reinterpret_cast<float*>(s_v)  [tid] = a1s + a2s;
        reinterpret_cast<float*>(s_m2u)[tid] = -2.f * (a1s * qv + a2s * qpv);

        s_b2[tid] = 2.f * biases[(size_t)b * N_ + tid];
        s_mk[tid] = mask  [(size_t)b * N_ + tid];
        if (tid + NTHR < N_) {
            s_b2[tid + NTHR] = 2.f * biases[(size_t)b * N_ + tid + NTHR];
            s_mk[tid + NTHR] = mask  [(size_t)b * N_ + tid + NTHR];
        }

        float c = a1s * qv * qv + a2s * qpv * qpv;
        #pragma unroll
        for (int o = 16; o; o >>= 1)
            c += __shfl_xor_sync(0xffffffffu, c, o);
        if (lane == 0) s_cq[warp] = c;
    }
    __syncthreads();

    const float4 vv = s_v[lane];
    const float4 mu = s_m2u[lane];
    const float  Cq = s_cq[0] + s_cq[1] + s_cq[2] + s_cq[3];

    auto body = [&](const float4 mv, const float4 cv, float& sa, float& so) {
        float t;
        t = fmaf(vv.x, mv.x, mu.x); sa = mv.x * t;
        t = fmaf(vv.y, mv.y, mu.y); sa = fmaf(mv.y, t, sa);
        t = fmaf(vv.z, mv.z, mu.z); sa = fmaf(mv.z, t, sa);
        t = fmaf(vv.w, mv.w, mu.w); sa = fmaf(mv.w, t, sa);
        t = fmaf(vv.x, cv.x, mu.x); so = cv.x * t;
        t = fmaf(vv.y, cv.y, mu.y); so = fmaf(cv.y, t, so);
        t = fmaf(vv.z, cv.z, mu.z); so = fmaf(cv.z, t, so);
        t = fmaf(vv.w, cv.w, mu.w); so = fmaf(cv.w, t, so);
    };

    auto finish1 = [&](int n, float sa, float so) {
        #pragma unroll
        for (int o = 16; o; o >>= 1) {
            sa += __shfl_xor_sync(0xffffffffu, sa, o);
            so += __shfl_xor_sync(0xffffffffu, so, o);
        }
        if (lane == 0) {
            const float add = Cq + s_b2[n];
            const float mk  = s_mk[n];
            s_logit[n] = -((sa + add) * mk);
            s_outd[n]  = (so + add) * mk;
        }
    };

    const unsigned FULL = 0xffffffffu;
    const bool lo16 = (lane & 16) == 0;
    const bool b3z  = (lane & 8)  == 0;
    const bool b2z  = (lane & 4)  == 0;
    const bool b1z  = (lane & 2)  == 0;

    auto reduceG = [&](int nb,
                       float sa0, float so0, float sa1, float so1,
                       float sa2, float so2, float sa3, float so3,
                       float sa4, float so4, float sa5, float so5,
                       float sa6, float so6, float sa7, float so7) {
        float A, B;
        A = sa0 + __shfl_xor_sync(FULL, sa0, 16);
        B = so0 + __shfl_xor_sync(FULL, so0, 16);
        const float r0 = lo16 ? A : B;
        A = sa1 + __shfl_xor_sync(FULL, sa1, 16);
        B = so1 + __shfl_xor_sync(FULL, so1, 16);
        const float r1 = lo16 ? A : B;
        A = sa2 + __shfl_xor_sync(FULL, sa2, 16);
        B = so2 + __shfl_xor_sync(FULL, so2, 16);
        const float r2 = lo16 ? A : B;
        A = sa3 + __shfl_xor_sync(FULL, sa3, 16);
        B = so3 + __shfl_xor_sync(FULL, so3, 16);
        const float r3 = lo16 ? A : B;
        A = sa4 + __shfl_xor_sync(FULL, sa4, 16);
        B = so4 + __shfl_xor_sync(FULL, so4, 16);
        const float r4 = lo16 ? A : B;
        A = sa5 + __shfl_xor_sync(FULL, sa5, 16);
        B = so5 + __shfl_xor_sync(FULL, so5, 16);
        const float r5 = lo16 ? A : B;
        A = sa6 + __shfl_xor_sync(FULL, sa6, 16);
        B = so6 + __shfl_xor_sync(FULL, so6, 16);
        const float r6 = lo16 ? A : B;
        A = sa7 + __shfl_xor_sync(FULL, sa7, 16);
        B = so7 + __shfl_xor_sync(FULL, so7, 16);
        const float r7 = lo16 ? A : B;

        A = r0 + __shfl_xor_sync(FULL, r0, 8);
        B = r1 + __shfl_xor_sync(FULL, r1, 8);
        const float s0 = b3z ? A : B;
        A = r2 + __shfl_xor_sync(FULL, r2, 8);
        B = r3 + __shfl_xor_sync(FULL, r3, 8);
        const float s1 = b3z ? A : B;
        A = r4 + __shfl_xor_sync(FULL, r4, 8);
        B = r5 + __shfl_xor_sync(FULL, r5, 8);
        const float s2 = b3z ? A : B;
        A = r6 + __shfl_xor_sync(FULL, r6, 8);
        B = r7 + __shfl_xor_sync(FULL, r7, 8);
        const float s3 = b3z ? A : B;

        A = s0 + __shfl_xor_sync(FULL, s0, 4);
        B = s1 + __shfl_xor_sync(FULL, s1, 4);
        const float t0 = b2z ? A : B;
        A = s2 + __shfl_xor_sync(FULL, s2, 4);
        B = s3 + __shfl_xor_sync(FULL, s3, 4);
        const float t1 = b2z ? A : B;

        A = t0 + __shfl_xor_sync(FULL, t0, 2);
        B = t1 + __shfl_xor_sync(FULL, t1, 2);
        const float u = b1z ? A : B;

        const float f = u + __shfl_xor_sync(FULL, u, 1);

        if ((lane & 1) == 0) {
            const int row = 4 * ((lane >> 1) & 1) + 2 * ((lane >> 2) & 1)
                          + ((lane >> 3) & 1);
            const int n   = nb + row * NWARP;
            const float val = (f + Cq + s_b2[n]) * s_mk[n];
            if (lo16) s_logit[n] = -val;
            else      s_outd[n]  =  val;
        }
    };

    // ── Group 0 (preloaded) ──
    {
        float sa0, so0, sa1, so1, sa2, so2, sa3, so3;
        float sa4, so4, sa5, so5, sa6, so6, sa7, so7;
        body(mv0, cv0, sa0, so0);
        body(mv1, cv1, sa1, so1);
        body(mv2, cv2, sa2, so2);
        body(mv3, cv3, sa3, so3);
        body(mv4, cv4, sa4, so4);
        body(mv5, cv5, sa5, so5);
        body(mv6, cv6, sa6, so6);
        body(mv7, cv7, sa7, so7);
        reduceG(nb0, sa0, so0, sa1, so1, sa2, so2, sa3, so3,
                     sa4, so4, sa5, so5, sa6, so6, sa7, so7);
    }

    // ── Groups 1..5 ──
    #pragma unroll 1
    for (int k = 8; k < 48; k += 8) {
        const int nb = warp + k * NWARP;

        const float4 Mv0 = m4[(nb + 0 * NWARP) * (E_ / 4) + lane];
        const float4 Mv1 = m4[(nb + 1 * NWARP) * (E_ / 4) + lane];
        const float4 Mv2 = m4[(nb + 2 * NWARP) * (E_ / 4) + lane];
        const float4 Mv3 = m4[(nb + 3 * NWARP) * (E_ / 4) + lane];
        const float4 Mv4 = m4[(nb + 4 * NWARP) * (E_ / 4) + lane];
        const float4 Mv5 = m4[(nb + 5 * NWARP) * (E_ / 4) + lane];
        const float4 Mv6 = m4[(nb + 6 * NWARP) * (E_ / 4) + lane];
        const float4 Mv7 = m4[(nb + 7 * NWARP) * (E_ / 4) + lane];
        const float4 Cv0 = c4[(nb + 0 * NWARP) * (E_ / 4) + lane];
        const float4 Cv1 = c4[(nb + 1 * NWARP) * (E_ / 4) + lane];
        const float4 Cv2 = c4[(nb + 2 * NWARP) * (E_ / 4) + lane];
        const float4 Cv3 = c4[(nb + 3 * NWARP) * (E_ / 4) + lane];
        const float4 Cv4 = c4[(nb + 4 * NWARP) * (E_ / 4) + lane];
        const float4 Cv5 = c4[(nb + 5 * NWARP) * (E_ / 4) + lane];
        const float4 Cv6 = c4[(nb + 6 * NWARP) * (E_ / 4) + lane];
        const float4 Cv7 = c4[(nb + 7 * NWARP) * (E_ / 4) + lane];

        float sa0, so0, sa1, so1, sa2, so2, sa3, so3;
        float sa4, so4, sa5, so5, sa6, so6, sa7, so7;
        body(Mv0, Cv0, sa0, so0);
        body(Mv1, Cv1, sa1, so1);
        body(Mv2, Cv2, sa2, so2);
        body(Mv3, Cv3, sa3, so3);
        body(Mv4, Cv4, sa4, so4);
        body(Mv5, Cv5, sa5, so5);
        body(Mv6, Cv6, sa6, so6);
        body(Mv7, Cv7, sa7, so7);

        reduceG(nb, sa0, so0, sa1, so1, sa2, so2, sa3, so3,
                    sa4, so4, sa5, so5, sa6, so6, sa7, so7);
    }
    // Tail rows j = 48, 49.
    {
        const int n0 = warp + 48 * NWARP;
        const int n1 = warp + 49 * NWARP;
        const float4 Mv0 = m4[n0 * (E_ / 4) + lane];
        const float4 Mv1 = m4[n1 * (E_ / 4) + lane];
        const float4 Cv0 = c4[n0 * (E_ / 4) + lane];
        const float4 Cv1 = c4[n1 * (E_ / 4) + lane];
        float sa0, so0, sa1, so1;
        body(Mv0, Cv0, sa0, so0);
        body(Mv1, Cv1, sa1, so1);
        finish1(n0, sa0, so0);
        finish1(n1, sa1, so1);
    }
    __syncthreads();

    // Block softmax over N_=200 with 128 threads.
    const int  n2ok = (tid + NTHR) < N_;
    const float v1 = s_logit[tid];
    const float v2 = n2ok ? s_logit[tid + NTHR] : -CUDART_INF_F;

    float wm = fmaxf(v1, v2);
    #pragma unroll
    for (int o = 16; o; o >>= 1)
        wm = fmaxf(wm, __shfl_xor_sync(0xffffffffu, wm, o));
    if (lane == 0) s_red[warp] = wm;
    __syncthreads();

    float mx = fmaxf(fmaxf(s_red[0], s_red[1]), fmaxf(s_red[2], s_red[3]));

    const float ex1 = __expf(v1 - mx);
    const float ex2 = n2ok ? __expf(v2 - mx) : 0.f;

    float ws = ex1 + ex2;
    #pragma unroll
    for (int o = 16; o; o >>= 1)
        ws += __shfl_xor_sync(0xffffffffu, ws, o);
    __syncthreads();
    if (lane == 0) s_red[warp] = ws;
    __syncthreads();

    const float inv = 1.f / (s_red[0] + s_red[1] + s_red[2] + s_red[3]);

    out[(size_t)b * N_ + tid] = s_outd[tid] * ex1 * inv;
    if (n2ok)
        out[(size_t)b * N_ + tid + NTHR] = s_outd[tid + NTHR] * ex2 * inv;
}

extern "C" void kernel_launch(void* const* d_in, const int* in_sizes, int n_in,
                              void* d_out, int out_size)
{
    const float* q      = (const float*)d_in[0];
    const float* q_p    = (const float*)d_in[1];
    const float* m      = (const float*)d_in[2];
    const float* m_c    = (const float*)d_in[3];
    const float* A1     = (const float*)d_in[4];
    const float* A2     = (const float*)d_in[5];
    const float* biases = (const float*)d_in[6];
    const float* mask   = (const float*)d_in[7];
    float* out = (float*)d_out;

    const int B = in_sizes[0] / E_;   // 1024
    mass_kernel<<<B, NTHR>>>(q, q_p, m, m_c, A1, A2, biases, mask, out);
}